// round 12
// baseline (speedup 1.0000x reference)
#include <cuda_runtime.h>
#include <stdint.h>

#define NN 100000
#define CC 128
#define EE 1600000
#define EPSV 1e-5f
#define MIS_ITERS 32

// ---------------- scratch (device globals; no allocation) ----------------
__device__ float g_agg[NN * CC];
__device__ float g_h0[NN * CC];
__device__ float g_h1[NN * CC];
__device__ float g_posagg[NN * 3];
__device__ int g_deg[NN];            // self-cleared by k_scan each replay
__device__ int g_rowptr[NN + 1];
__device__ int g_cursor[NN];
__device__ int g_col[EE];
__device__ float g_wgt[EE];
__device__ unsigned long long g_key[NN];
__device__ unsigned long long g_akey[NN];
__device__ unsigned long long g_nmax[NN];
__device__ unsigned long long g_nmax2[NN];
__device__ unsigned char g_block[NN];   // MIS: self-loop flag; then pool write-flag
__device__ unsigned char g_mis[NN];
__device__ int g_cluster[NN];
__device__ int2 g_elA[EE];
__device__ int2 g_elB[EE];
__device__ int g_ecnt[2];
__device__ double g_sum[CC];
__device__ double g_sumsq[CC];
__device__ float g_scale[CC];
__device__ float g_shift[CC];
__device__ int g_barcnt;
__device__ int g_barrel;

// ---------------- CSR build ----------------
__global__ void k_hist(const int* __restrict__ dst) {
    int e = blockIdx.x * blockDim.x + threadIdx.x;
    if (e < EE) atomicAdd(&g_deg[dst[e]], 1);
}

__global__ void __launch_bounds__(1024) k_scan() {
    __shared__ int part[1024];
    int tid = threadIdx.x;
    const int CH = (NN + 1023) / 1024;
    int base = tid * CH;
    int sum = 0;
    for (int i = 0; i < CH; i++) {
        int idx = base + i;
        if (idx < NN) sum += g_deg[idx];
    }
    part[tid] = sum;
    __syncthreads();
    for (int off = 1; off < 1024; off <<= 1) {
        int v = (tid >= off) ? part[tid - off] : 0;
        __syncthreads();
        part[tid] += v;
        __syncthreads();
    }
    int run = (tid == 0) ? 0 : part[tid - 1];
    for (int i = 0; i < CH; i++) {
        int idx = base + i;
        if (idx < NN) {
            g_rowptr[idx] = run;
            g_cursor[idx] = run;
            run += g_deg[idx];
            g_deg[idx] = 0;   // self-clear: next replay's k_hist accumulates onto zeros
        }
    }
    if (tid == 1023) g_rowptr[NN] = run;
}

__global__ void k_scatter(const int* __restrict__ src, const int* __restrict__ dst,
                          const float* __restrict__ ew) {
    int e = blockIdx.x * blockDim.x + threadIdx.x;
    if (e >= EE) return;
    int d = dst[e];
    int idx = atomicAdd(&g_cursor[d], 1);
    g_col[idx] = src[e];
    g_wgt[idx] = ew[e];
}

// ---------------- BN apply helpers ----------------
__device__ __forceinline__ float4 bn4s(float4 v, float4 sc, float4 sh) {
    v.x = fmaxf(fmaf(v.x, sc.x, sh.x), 0.f);
    v.y = fmaxf(fmaf(v.y, sc.y, sh.y), 0.f);
    v.z = fmaxf(fmaf(v.z, sc.z, sh.z), 0.f);
    v.w = fmaxf(fmaf(v.w, sc.w, sh.w), 0.f);
    return v;
}
__device__ __forceinline__ float4 bn4(float4 v, int ch) {
    return bn4s(v, *(const float4*)(g_scale + ch), *(const float4*)(g_shift + ch));
}

// ---------------- pull-SpMM ----------------
__global__ void __launch_bounds__(256) k_spmm_pull(const float* __restrict__ xin,
                                                   const float* __restrict__ pos,
                                                   int bn) {
    const float* x = xin ? xin : g_h0;
    int gt = blockIdx.x * 256 + threadIdx.x;
    int node = gt >> 5, lane = gt & 31;
    if (node >= NN) return;
    int e0 = g_rowptr[node], e1 = g_rowptr[node + 1];
    float4 sc = make_float4(0.f, 0.f, 0.f, 0.f), sh = sc;
    if (bn) { sc = *(const float4*)(g_scale + lane * 4); sh = *(const float4*)(g_shift + lane * 4); }
    float4 acc = make_float4(0.f, 0.f, 0.f, 0.f);
    bool dopos = (pos != nullptr) && (lane < 3);
    float pacc = 0.f;
    float pd = dopos ? pos[node * 3 + lane] : 0.f;
    int scur = 0; float wcur = 0.f;
    if (e0 < e1) { scur = g_col[e0]; wcur = g_wgt[e0]; }
    for (int e = e0; e < e1; e++) {
        int snx = 0; float wnx = 0.f;
        if (e + 1 < e1) { snx = g_col[e + 1]; wnx = g_wgt[e + 1]; }
        float4 v = *(const float4*)(x + (size_t)scur * CC + lane * 4);
        if (bn) v = bn4s(v, sc, sh);
        acc.x += wcur * v.x; acc.y += wcur * v.y;
        acc.z += wcur * v.z; acc.w += wcur * v.w;
        if (dopos) pacc += wcur * (pos[scur * 3 + lane] - pd);
        scur = snx; wcur = wnx;
    }
    *(float4*)(g_agg + (size_t)node * CC + lane * 4) = acc;
    if (dopos) g_posagg[node * 3 + lane] = pacc;
}

// ---------------- double-buffered fused GEMM + BN stats (f32x2, R10 proven) -------
__global__ void __launch_bounds__(256, 2) k_gemm(const float* __restrict__ Xin,
                                                 const float* __restrict__ Wr,
                                                 const float* __restrict__ Wm,
                                                 const float* __restrict__ Wp,
                                                 const float* __restrict__ bias,
                                                 int outsel, int bnA) {
    __shared__ __align__(16) float As[2][8][128];
    __shared__ __align__(16) float Bs[2][8][128];
    __shared__ float cs[128], cq[128];
    const float* X = Xin ? Xin : g_h0;
    float* outp = outsel ? g_h1 : g_h0;
    int bm = blockIdx.x * 128;
    int tid = threadIdx.x;
    if (tid < 128) { cs[tid] = 0.f; cq[tid] = 0.f; }
    int tx = tid & 15, ty = tid >> 4;
    int am = tid >> 1, ak = (tid & 1) * 4;
    int kb = tid >> 5, bc = (tid & 31) * 4;
    int arow = bm + am;
    bool aval = arow < NN;

    unsigned long long acc2[8][4];
#pragma unroll
    for (int i = 0; i < 8; i++)
#pragma unroll
        for (int jp = 0; jp < 4; jp++) acc2[i][jp] = 0ULL;

    float4 areg;
    {
        const float* gp = Wr + (size_t)kb * CC + bc;
        unsigned sa = (unsigned)__cvta_generic_to_shared(&Bs[0][kb][bc]);
        asm volatile("cp.async.ca.shared.global [%0], [%1], 16;" :: "r"(sa), "l"(gp));
        asm volatile("cp.async.commit_group;");
        areg = make_float4(0.f, 0.f, 0.f, 0.f);
        if (aval) {
            areg = *(const float4*)(X + (size_t)arow * CC + ak);
            if (bnA) areg = bn4(areg, ak);
        }
        As[0][ak + 0][am] = areg.x; As[0][ak + 1][am] = areg.y;
        As[0][ak + 2][am] = areg.z; As[0][ak + 3][am] = areg.w;
        asm volatile("cp.async.wait_group 0;");
    }
    __syncthreads();

    for (int kt = 0; kt < 256; kt += 8) {
        int s = (kt >> 3) & 1;
        bool more = (kt + 8) < 256;
        if (more) {
            int kn = kt + 8;
            const float* SB = (kn < 128) ? Wr : Wm;
            const float* gp = SB + (size_t)((kn + kb) & 127) * CC + bc;
            unsigned sa = (unsigned)__cvta_generic_to_shared(&Bs[s ^ 1][kb][bc]);
            asm volatile("cp.async.ca.shared.global [%0], [%1], 16;" :: "r"(sa), "l"(gp));
            asm volatile("cp.async.commit_group;");
            areg = make_float4(0.f, 0.f, 0.f, 0.f);
            if (aval) {
                const float* SA = (kn < 128) ? X : g_agg;
                areg = *(const float4*)(SA + (size_t)arow * CC + ((kn + ak) & 127));
                if (bnA && kn < 128) areg = bn4(areg, kn + ak);
            }
        }
#pragma unroll
        for (int k = 0; k < 8; k++) {
            float a[8];
            *(float4*)&a[0] = *(const float4*)&As[s][k][ty * 8];
            *(float4*)&a[4] = *(const float4*)&As[s][k][ty * 8 + 4];
            ulonglong2 b01 = *(const ulonglong2*)&Bs[s][k][tx * 8];
            ulonglong2 b23 = *(const ulonglong2*)&Bs[s][k][tx * 8 + 4];
            unsigned long long bp0 = b01.x, bp1 = b01.y, bp2 = b23.x, bp3 = b23.y;
#pragma unroll
            for (int i = 0; i < 8; i++) {
                unsigned long long aa;
                asm("mov.b64 %0, {%1, %1};" : "=l"(aa) : "f"(a[i]));
                asm("fma.rn.f32x2 %0, %1, %2, %0;" : "+l"(acc2[i][0]) : "l"(aa), "l"(bp0));
                asm("fma.rn.f32x2 %0, %1, %2, %0;" : "+l"(acc2[i][1]) : "l"(aa), "l"(bp1));
                asm("fma.rn.f32x2 %0, %1, %2, %0;" : "+l"(acc2[i][2]) : "l"(aa), "l"(bp2));
                asm("fma.rn.f32x2 %0, %1, %2, %0;" : "+l"(acc2[i][3]) : "l"(aa), "l"(bp3));
            }
        }
        if (more) {
            As[s ^ 1][ak + 0][am] = areg.x; As[s ^ 1][ak + 1][am] = areg.y;
            As[s ^ 1][ak + 2][am] = areg.z; As[s ^ 1][ak + 3][am] = areg.w;
            asm volatile("cp.async.wait_group 0;");
        }
        __syncthreads();
    }

    float bb[8], wp0[8], wp1[8], wp2[8];
#pragma unroll
    for (int j = 0; j < 8; j++) {
        int col = tx * 8 + j;
        bb[j] = bias[col]; wp0[j] = Wp[col]; wp1[j] = Wp[CC + col]; wp2[j] = Wp[2 * CC + col];
    }
    float s_[8], q_[8];
#pragma unroll
    for (int j = 0; j < 8; j++) { s_[j] = 0.f; q_[j] = 0.f; }
#pragma unroll
    for (int i = 0; i < 8; i++) {
        int row = bm + ty * 8 + i;
        if (row < NN) {
            float p0 = g_posagg[row * 3 + 0], p1 = g_posagg[row * 3 + 1], p2 = g_posagg[row * 3 + 2];
            float r[8];
#pragma unroll
            for (int jp = 0; jp < 4; jp++) {
                float2 v = *(float2*)&acc2[i][jp];
                r[2 * jp + 0] = v.x;
                r[2 * jp + 1] = v.y;
            }
#pragma unroll
            for (int j = 0; j < 8; j++) {
                float t = r[j] + bb[j] + p0 * wp0[j] + p1 * wp1[j] + p2 * wp2[j];
                r[j] = t; s_[j] += t; q_[j] += t * t;
            }
            *(float4*)(outp + (size_t)row * CC + tx * 8) = make_float4(r[0], r[1], r[2], r[3]);
            *(float4*)(outp + (size_t)row * CC + tx * 8 + 4) = make_float4(r[4], r[5], r[6], r[7]);
        }
    }
#pragma unroll
    for (int j = 0; j < 8; j++) {
        atomicAdd(&cs[tx * 8 + j], s_[j]);
        atomicAdd(&cq[tx * 8 + j], q_[j]);
    }
    __syncthreads();
    if (tid < 128) {
        atomicAdd(&g_sum[tid], (double)cs[tid]);
        atomicAdd(&g_sumsq[tid], (double)cq[tid]);
    }
}

// ---------------- BatchNorm finalize (separate tiny kernel; R10 proven) ----------
__global__ void k_bnfin(const float* __restrict__ g, const float* __restrict__ be) {
    int c = threadIdx.x;
    float mu = (float)(g_sum[c] / NN);
    float var = (float)(g_sumsq[c] / NN) - mu * mu;
    float sc = g[c] * rsqrtf(var + EPSV);
    g_scale[c] = sc;
    g_shift[c] = be[c] - mu * sc;
    g_sum[c] = 0.0;
    g_sumsq[c] = 0.0;
}

// layer 1: BN+ReLU + score key + MIS node-state init (warp per node)
__global__ void __launch_bounds__(256) k_bnrelu_key(const float* __restrict__ ws) {
    int gt = blockIdx.x * 256 + threadIdx.x;
    int node = gt >> 5, lane = gt & 31;
    if (node >= NN) return;
    int c = lane * 4;
    float4 v = bn4(*(float4*)(g_h1 + (size_t)node * CC + c), c);
    *(float4*)(g_h1 + (size_t)node * CC + c) = v;
    float4 w = *(const float4*)(ws + c);
    float p = v.x * w.x + v.y * w.y + v.z * w.z + v.w * w.w;
#pragma unroll
    for (int o = 16; o; o >>= 1) p += __shfl_xor_sync(0xFFFFFFFFu, p, o);
    if (lane == 0) {
        unsigned u = __float_as_uint(p);
        u = (u & 0x80000000u) ? ~u : (u | 0x80000000u);
        unsigned long long key = ((unsigned long long)u << 32) | (unsigned)(NN - 1 - node);
        g_key[node] = key;
        g_akey[node] = key;
        g_nmax[node] = 0ULL;
        g_nmax2[node] = 0ULL;
        g_mis[node] = 0;
        g_block[node] = 0;
        if (node == 0) { g_ecnt[0] = 0; g_ecnt[1] = 0; }
    }
}

// ---------------- software grid barrier (R6/R10 version) ----------------
__device__ __forceinline__ void gbar(int nb, int& epoch) {
    __syncthreads();
    if (threadIdx.x == 0) {
        __threadfence();
        if (atomicAdd(&g_barcnt, 1) == nb - 1) {
            atomicExch(&g_barcnt, 0);
            __threadfence();
            atomicExch(&g_barrel, epoch + 1);
        } else {
            while (atomicAdd(&g_barrel, 0) < epoch + 1) __nanosleep(32);
        }
        __threadfence();
    }
    __syncthreads();
    epoch++;
}

// warp-aggregated append; ALL 32 lanes must call (full-mask ballot)
__device__ __forceinline__ void wappend(bool pred, int2 p, int2* outl, int* outc, int lane) {
    unsigned mask = __ballot_sync(0xFFFFFFFFu, pred);
    if (pred) {
        int leader = __ffs(mask) - 1;
        int base = 0;
        if (lane == leader) base = atomicAdd(outc, __popc(mask));
        base = __shfl_sync(mask, base, leader);
        outl[base + __popc(mask & ((1u << lane) - 1))] = p;
    }
}

// ---------------- fused persistent MIS + best-neighbor + cluster decode ----------
__global__ void __launch_bounds__(512) k_mis_fused(const int* __restrict__ src,
                                                   const int* __restrict__ dst) {
    const int nb = gridDim.x;
    const int nt = nb * 512;
    const int gt = blockIdx.x * 512 + threadIdx.x;
    const int lane = threadIdx.x & 31;
    __shared__ int s_cnt, s_ep;
    if (threadIdx.x == 0) s_ep = atomicAdd(&g_barrel, 0);
    __syncthreads();
    int epoch = s_ep;

    for (int e = gt; e < EE; e += nt) {
        int s = src[e], d = dst[e];
        if (s == d) { g_block[s] = 1; continue; }
        atomicMax(&g_nmax[d], g_key[s]);
        atomicMax(&g_nmax[s], g_key[d]);
    }
    gbar(nb, epoch);
    for (int e = gt; e < EE; e += nt) {
        int s = src[e], d = dst[e];
        if (s == d) continue;
        if (!g_block[s] && g_akey[s] > g_nmax[s]) { g_mis[s] = 1; g_akey[d] = 0; }
        if (!g_block[d] && g_akey[d] > g_nmax[d]) { g_mis[d] = 1; g_akey[s] = 0; }
    }
    gbar(nb, epoch);

    int prev = EE + 1;
    unsigned long long* nmaxLast = g_nmax;
    for (int t = 1; t < MIS_ITERS; t++) {
        int ob = t & 1;
        unsigned long long* nmaxC = ob ? g_nmax2 : g_nmax;
        unsigned long long* nmaxN = ob ? g_nmax : g_nmax2;
        int2* outl = ob ? g_elB : g_elA;
        int* outc = &g_ecnt[ob];
        if (t == 1) {
            for (int e = gt; e - lane < EE; e += nt) {
                bool in = e < EE;
                int2 p = make_int2(0, 0);
                bool live = false;
                if (in) {
                    p.x = src[e]; p.y = dst[e];
                    if (p.x != p.y) {
                        unsigned long long ks = g_akey[p.x], kd = g_akey[p.y];
                        if (ks && kd && !g_mis[p.x] && !g_mis[p.y]) {
                            live = true;
                            atomicMax(&nmaxC[p.y], ks);
                            atomicMax(&nmaxC[p.x], kd);
                        }
                    }
                }
                wappend(live, p, outl, outc, lane);
            }
        } else {
            const int2* inl = ob ? g_elA : g_elB;
            int cin = g_ecnt[1 - ob];
            for (int e = gt; e - lane < cin; e += nt) {
                bool in = e < cin;
                int2 p = make_int2(0, 0);
                bool live = false;
                if (in) {
                    p = inl[e];
                    unsigned long long ks = g_akey[p.x], kd = g_akey[p.y];
                    if (ks && kd && !g_mis[p.x] && !g_mis[p.y]) {
                        live = true;
                        atomicMax(&nmaxC[p.y], ks);
                        atomicMax(&nmaxC[p.x], kd);
                    }
                }
                wappend(live, p, outl, outc, lane);
            }
        }
        gbar(nb, epoch);
        if (threadIdx.x == 0) s_cnt = g_ecnt[ob];
        __syncthreads();
        int cnt = s_cnt;
        nmaxLast = nmaxC;
        if (cnt == 0 || cnt == prev) break;
        prev = cnt;
        if (gt == 0) g_ecnt[1 - ob] = 0;
        for (int e = gt; e < cnt; e += nt) {
            int2 p = outl[e];
            if (!g_block[p.x] && g_akey[p.x] > nmaxC[p.x]) { g_mis[p.x] = 1; g_akey[p.y] = 0; }
            if (!g_block[p.y] && g_akey[p.y] > nmaxC[p.y]) { g_mis[p.y] = 1; g_akey[p.x] = 0; }
        }
        for (int i = gt; i < NN; i += nt) nmaxN[i] = 0ULL;
        gbar(nb, epoch);
    }

    // isolated actives -> MIS; clear g_nmax for best-neighbor pass
    for (int i = gt; i < NN; i += nt) {
        bool iso = g_akey[i] && !g_mis[i] && !g_block[i] && (nmaxLast[i] == 0ULL);
        if (iso) g_mis[i] = 1;
        g_nmax[i] = 0ULL;
    }
    gbar(nb, epoch);
    // best MIS neighbor by key over original edge arrays
    for (int e = gt; e < EE; e += nt) {
        int s = src[e], d = dst[e];
        if (g_mis[s]) atomicMax(&g_nmax[d], g_key[s]);
        if (g_mis[d]) atomicMax(&g_nmax[s], g_key[d]);
    }
    gbar(nb, epoch);
    // cluster decode + pool write-flag (g_block reused: MIS phase done)
    for (int i = gt; i < NN; i += nt) {
        int cl; unsigned char wf;
        if (g_mis[i]) { cl = i; wf = 1; }
        else {
            unsigned long long b = g_nmax[i];
            if (b) { cl = NN - 1 - (int)(unsigned)(b & 0xFFFFFFFFULL); wf = 1; }
            else { cl = i; wf = 0; }
        }
        g_cluster[i] = cl;
        g_block[i] = wf;
    }
}

// ---------------- merged zero + tail outputs ----------------
__global__ void k_ztail(float* __restrict__ out, const int* __restrict__ src,
                        const int* __restrict__ dst, const float* __restrict__ ew,
                        const float* __restrict__ pos, int out_size) {
    int stride = gridDim.x * blockDim.x;
    for (int t = blockIdx.x * blockDim.x + threadIdx.x; t < NN * CC / 4; t += stride) {
        if (4 * t + 3 < out_size)
            ((float4*)out)[t] = make_float4(0.f, 0.f, 0.f, 0.f);
    }
    const int O1 = NN * CC;
    const int TAIL = 3 * EE + 5 * NN;
    for (int t = blockIdx.x * blockDim.x + threadIdx.x; t < TAIL; t += stride) {
        int o = O1 + t;
        if (o >= out_size) return;
        float val;
        if (t < EE) {
            val = (float)g_cluster[src[t]];
        } else if (t < 2 * EE) {
            val = (float)g_cluster[dst[t - EE]];
        } else if (t < 3 * EE) {
            val = ew[t - 2 * EE];
        } else if (t < 3 * EE + 3 * NN) {
            int j = t - 3 * EE;
            val = g_mis[j / 3] ? pos[j] : 0.f;
        } else if (t < 3 * EE + 4 * NN) {
            val = 0.f;  // batch
        } else {
            val = g_mis[t - (3 * EE + 4 * NN)] ? 1.f : 0.f;
        }
        out[o] = val;
    }
}

// pool: precomputed cluster + write-flag; h1>=0 so int-bits atomicMax
__global__ void __launch_bounds__(256) k_pool(float* __restrict__ out) {
    int gt = blockIdx.x * 256 + threadIdx.x;
    int node = gt >> 5, lane = gt & 31;
    if (node >= NN) return;
    if (!g_block[node]) return;   // orphan self-cluster: row stays zero
    int cl = g_cluster[node];
    float4 v = *(const float4*)(g_h1 + (size_t)node * CC + lane * 4);
    int* p = (int*)(out + (size_t)cl * CC + lane * 4);
    atomicMax(p + 0, __float_as_int(v.x));
    atomicMax(p + 1, __float_as_int(v.y));
    atomicMax(p + 2, __float_as_int(v.z));
    atomicMax(p + 3, __float_as_int(v.w));
}

// ---------------- launch ----------------
extern "C" void kernel_launch(void* const* d_in, const int* in_sizes, int n_in,
                              void* d_out, int out_size) {
    const float* x   = (const float*)d_in[0];
    const int*   ei  = (const int*)d_in[1];
    const float* ew  = (const float*)d_in[2];
    const float* pos = (const float*)d_in[3];
    const float* Wr0 = (const float*)d_in[5];
    const float* Wm0 = (const float*)d_in[6];
    const float* Wp0 = (const float*)d_in[7];
    const float* b0  = (const float*)d_in[8];
    const float* g0  = (const float*)d_in[9];
    const float* be0 = (const float*)d_in[10];
    const float* Wr1 = (const float*)d_in[11];
    const float* Wm1 = (const float*)d_in[12];
    const float* Wp1 = (const float*)d_in[13];
    const float* b1  = (const float*)d_in[14];
    const float* g1  = (const float*)d_in[15];
    const float* be1 = (const float*)d_in[16];
    const float* wsc = (const float*)d_in[17];
    float* out = (float*)d_out;

    const int E = in_sizes[1] / 2;
    const int* src = ei;
    const int* dst = ei + E;
    (void)E;

    int sms = 148;
    cudaDeviceGetAttribute(&sms, cudaDevAttrMultiProcessorCount, 0);

    const int EB    = (EE + 255) / 256;
    const int NWARP = (NN * 32 + 255) / 256;
    const int GGRID = (NN + 127) / 128;

    // ---- CSR build (g_deg zeroed at init; self-cleared each replay by k_scan) ----
    k_hist<<<EB, 256>>>(dst);
    k_scan<<<1, 1024>>>();
    k_scatter<<<EB, 256>>>(src, dst, ew);

    // ---- layer 0 ----
    k_spmm_pull<<<NWARP, 256>>>(x, pos, 0);
    k_gemm<<<GGRID, 256>>>(x, Wr0, Wm0, Wp0, b0, 0, 0);
    k_bnfin<<<1, 128>>>(g0, be0);

    // ---- layer 1 ----
    k_spmm_pull<<<NWARP, 256>>>(nullptr, nullptr, 1);
    k_gemm<<<GGRID, 256>>>(nullptr, Wr1, Wm1, Wp1, b1, 1, 1);
    k_bnfin<<<1, 128>>>(g1, be1);
    k_bnrelu_key<<<NWARP, 256>>>(wsc);

    // ---- fused persistent MIS + best-neighbor + cluster decode ----
    k_mis_fused<<<sms, 512>>>(src, dst);

    // ---- outputs: zero+tail, then pool ----
    k_ztail<<<2048, 256>>>(out, src, dst, ew, pos, out_size);
    k_pool<<<NWARP, 256>>>(out);
}

// round 13
// speedup vs baseline: 1.0083x; 1.0083x over previous
#include <cuda_runtime.h>
#include <stdint.h>

#define NN 100000
#define CC 128
#define EE 1600000
#define EPSV 1e-5f
#define MIS_ITERS 32

// ---------------- scratch (device globals; no allocation) ----------------
__device__ float g_agg[NN * CC];
__device__ float g_h0[NN * CC];
__device__ float g_h1[NN * CC];
__device__ float g_posagg[NN * 3];
__device__ int g_deg[NN];            // zero at init; self-cleared by k_scan each replay
__device__ int g_rowptr[NN + 1];
__device__ int g_cursor[NN];
__device__ int g_col[EE];
__device__ float g_wgt[EE];
__device__ unsigned long long g_key[NN];
__device__ unsigned long long g_akey[NN];
__device__ unsigned long long g_nmax[NN];
__device__ unsigned long long g_nmax2[NN];
__device__ unsigned char g_block[NN];
__device__ unsigned char g_mis[NN];
__device__ int g_cluster[NN];
__device__ int2 g_elA[EE];
__device__ int2 g_elB[EE];
__device__ int g_ecnt[2];
__device__ double g_sum[CC];
__device__ double g_sumsq[CC];
__device__ float g_scale[CC];
__device__ float g_shift[CC];
__device__ int g_barcnt;
__device__ int g_barrel;

// ---------------- CSR build + MIS-independent output prep ----------------
// hist is atomic-issue-bound with idle DRAM bandwidth: fold in the out-buffer
// writes that depend on nothing (zero x_pool region, ew copy, batch zeros).
__global__ void k_hist(const int* __restrict__ dst, float* __restrict__ out,
                       const float* __restrict__ ew, int out_size) {
    int gt = blockIdx.x * blockDim.x + threadIdx.x;
    int stride = gridDim.x * blockDim.x;
    if (gt < EE) atomicAdd(&g_deg[dst[gt]], 1);
    // zero x_pool region [0, NN*CC)
    for (int t = gt; t < NN * CC / 4; t += stride) {
        if (4 * t + 3 < out_size)
            ((float4*)out)[t] = make_float4(0.f, 0.f, 0.f, 0.f);
    }
    // ew copy: out[NN*CC + 2*EE + e] = ew[e]
    {
        const int base = NN * CC + 2 * EE;
        for (int e = gt; e < EE; e += stride) {
            int o = base + e;
            if (o < out_size) out[o] = ew[e];
        }
    }
    // batch zeros: out[NN*CC + 3*EE + 3*NN .. +4*NN)
    {
        const int base = NN * CC + 3 * EE + 3 * NN;
        for (int t = gt; t < NN; t += stride) {
            int o = base + t;
            if (o < out_size) out[o] = 0.f;
        }
    }
}

__global__ void __launch_bounds__(1024) k_scan() {
    __shared__ int part[1024];
    int tid = threadIdx.x;
    const int CH = (NN + 1023) / 1024;
    int base = tid * CH;
    int sum = 0;
    for (int i = 0; i < CH; i++) {
        int idx = base + i;
        if (idx < NN) sum += g_deg[idx];
    }
    part[tid] = sum;
    __syncthreads();
    for (int off = 1; off < 1024; off <<= 1) {
        int v = (tid >= off) ? part[tid - off] : 0;
        __syncthreads();
        part[tid] += v;
        __syncthreads();
    }
    int run = (tid == 0) ? 0 : part[tid - 1];
    for (int i = 0; i < CH; i++) {
        int idx = base + i;
        if (idx < NN) {
            g_rowptr[idx] = run;
            g_cursor[idx] = run;
            run += g_deg[idx];
            g_deg[idx] = 0;   // self-clear: next replay's k_hist accumulates onto zeros
        }
    }
    if (tid == 1023) g_rowptr[NN] = run;
}

__global__ void k_scatter(const int* __restrict__ src, const int* __restrict__ dst,
                          const float* __restrict__ ew) {
    int e = blockIdx.x * blockDim.x + threadIdx.x;
    if (e >= EE) return;
    int d = dst[e];
    int idx = atomicAdd(&g_cursor[d], 1);
    g_col[idx] = src[e];
    g_wgt[idx] = ew[e];
}

// ---------------- BN apply helpers ----------------
__device__ __forceinline__ float4 bn4s(float4 v, float4 sc, float4 sh) {
    v.x = fmaxf(fmaf(v.x, sc.x, sh.x), 0.f);
    v.y = fmaxf(fmaf(v.y, sc.y, sh.y), 0.f);
    v.z = fmaxf(fmaf(v.z, sc.z, sh.z), 0.f);
    v.w = fmaxf(fmaf(v.w, sc.w, sh.w), 0.f);
    return v;
}
__device__ __forceinline__ float4 bn4(float4 v, int ch) {
    return bn4s(v, *(const float4*)(g_scale + ch), *(const float4*)(g_shift + ch));
}

// ---------------- pull-SpMM (R10 proven) ----------------
__global__ void __launch_bounds__(256) k_spmm_pull(const float* __restrict__ xin,
                                                   const float* __restrict__ pos,
                                                   int bn) {
    const float* x = xin ? xin : g_h0;
    int gt = blockIdx.x * 256 + threadIdx.x;
    int node = gt >> 5, lane = gt & 31;
    if (node >= NN) return;
    int e0 = g_rowptr[node], e1 = g_rowptr[node + 1];
    float4 sc = make_float4(0.f, 0.f, 0.f, 0.f), sh = sc;
    if (bn) { sc = *(const float4*)(g_scale + lane * 4); sh = *(const float4*)(g_shift + lane * 4); }
    float4 acc = make_float4(0.f, 0.f, 0.f, 0.f);
    bool dopos = (pos != nullptr) && (lane < 3);
    float pacc = 0.f;
    float pd = dopos ? pos[node * 3 + lane] : 0.f;
    int scur = 0; float wcur = 0.f;
    if (e0 < e1) { scur = g_col[e0]; wcur = g_wgt[e0]; }
    for (int e = e0; e < e1; e++) {
        int snx = 0; float wnx = 0.f;
        if (e + 1 < e1) { snx = g_col[e + 1]; wnx = g_wgt[e + 1]; }
        float4 v = *(const float4*)(x + (size_t)scur * CC + lane * 4);
        if (bn) v = bn4s(v, sc, sh);
        acc.x += wcur * v.x; acc.y += wcur * v.y;
        acc.z += wcur * v.z; acc.w += wcur * v.w;
        if (dopos) pacc += wcur * (pos[scur * 3 + lane] - pd);
        scur = snx; wcur = wnx;
    }
    *(float4*)(g_agg + (size_t)node * CC + lane * 4) = acc;
    if (dopos) g_posagg[node * 3 + lane] = pacc;
}

// ---------------- double-buffered fused GEMM + BN stats (f32x2, R10 proven) -------
__global__ void __launch_bounds__(256, 2) k_gemm(const float* __restrict__ Xin,
                                                 const float* __restrict__ Wr,
                                                 const float* __restrict__ Wm,
                                                 const float* __restrict__ Wp,
                                                 const float* __restrict__ bias,
                                                 int outsel, int bnA) {
    __shared__ __align__(16) float As[2][8][128];
    __shared__ __align__(16) float Bs[2][8][128];
    __shared__ float cs[128], cq[128];
    const float* X = Xin ? Xin : g_h0;
    float* outp = outsel ? g_h1 : g_h0;
    int bm = blockIdx.x * 128;
    int tid = threadIdx.x;
    if (tid < 128) { cs[tid] = 0.f; cq[tid] = 0.f; }
    int tx = tid & 15, ty = tid >> 4;
    int am = tid >> 1, ak = (tid & 1) * 4;
    int kb = tid >> 5, bc = (tid & 31) * 4;
    int arow = bm + am;
    bool aval = arow < NN;

    unsigned long long acc2[8][4];
#pragma unroll
    for (int i = 0; i < 8; i++)
#pragma unroll
        for (int jp = 0; jp < 4; jp++) acc2[i][jp] = 0ULL;

    float4 areg;
    {
        const float* gp = Wr + (size_t)kb * CC + bc;
        unsigned sa = (unsigned)__cvta_generic_to_shared(&Bs[0][kb][bc]);
        asm volatile("cp.async.ca.shared.global [%0], [%1], 16;" :: "r"(sa), "l"(gp));
        asm volatile("cp.async.commit_group;");
        areg = make_float4(0.f, 0.f, 0.f, 0.f);
        if (aval) {
            areg = *(const float4*)(X + (size_t)arow * CC + ak);
            if (bnA) areg = bn4(areg, ak);
        }
        As[0][ak + 0][am] = areg.x; As[0][ak + 1][am] = areg.y;
        As[0][ak + 2][am] = areg.z; As[0][ak + 3][am] = areg.w;
        asm volatile("cp.async.wait_group 0;");
    }
    __syncthreads();

    for (int kt = 0; kt < 256; kt += 8) {
        int s = (kt >> 3) & 1;
        bool more = (kt + 8) < 256;
        if (more) {
            int kn = kt + 8;
            const float* SB = (kn < 128) ? Wr : Wm;
            const float* gp = SB + (size_t)((kn + kb) & 127) * CC + bc;
            unsigned sa = (unsigned)__cvta_generic_to_shared(&Bs[s ^ 1][kb][bc]);
            asm volatile("cp.async.ca.shared.global [%0], [%1], 16;" :: "r"(sa), "l"(gp));
            asm volatile("cp.async.commit_group;");
            areg = make_float4(0.f, 0.f, 0.f, 0.f);
            if (aval) {
                const float* SA = (kn < 128) ? X : g_agg;
                areg = *(const float4*)(SA + (size_t)arow * CC + ((kn + ak) & 127));
                if (bnA && kn < 128) areg = bn4(areg, kn + ak);
            }
        }
#pragma unroll
        for (int k = 0; k < 8; k++) {
            float a[8];
            *(float4*)&a[0] = *(const float4*)&As[s][k][ty * 8];
            *(float4*)&a[4] = *(const float4*)&As[s][k][ty * 8 + 4];
            ulonglong2 b01 = *(const ulonglong2*)&Bs[s][k][tx * 8];
            ulonglong2 b23 = *(const ulonglong2*)&Bs[s][k][tx * 8 + 4];
            unsigned long long bp0 = b01.x, bp1 = b01.y, bp2 = b23.x, bp3 = b23.y;
#pragma unroll
            for (int i = 0; i < 8; i++) {
                unsigned long long aa;
                asm("mov.b64 %0, {%1, %1};" : "=l"(aa) : "f"(a[i]));
                asm("fma.rn.f32x2 %0, %1, %2, %0;" : "+l"(acc2[i][0]) : "l"(aa), "l"(bp0));
                asm("fma.rn.f32x2 %0, %1, %2, %0;" : "+l"(acc2[i][1]) : "l"(aa), "l"(bp1));
                asm("fma.rn.f32x2 %0, %1, %2, %0;" : "+l"(acc2[i][2]) : "l"(aa), "l"(bp2));
                asm("fma.rn.f32x2 %0, %1, %2, %0;" : "+l"(acc2[i][3]) : "l"(aa), "l"(bp3));
            }
        }
        if (more) {
            As[s ^ 1][ak + 0][am] = areg.x; As[s ^ 1][ak + 1][am] = areg.y;
            As[s ^ 1][ak + 2][am] = areg.z; As[s ^ 1][ak + 3][am] = areg.w;
            asm volatile("cp.async.wait_group 0;");
        }
        __syncthreads();
    }

    float bb[8], wp0[8], wp1[8], wp2[8];
#pragma unroll
    for (int j = 0; j < 8; j++) {
        int col = tx * 8 + j;
        bb[j] = bias[col]; wp0[j] = Wp[col]; wp1[j] = Wp[CC + col]; wp2[j] = Wp[2 * CC + col];
    }
    float s_[8], q_[8];
#pragma unroll
    for (int j = 0; j < 8; j++) { s_[j] = 0.f; q_[j] = 0.f; }
#pragma unroll
    for (int i = 0; i < 8; i++) {
        int row = bm + ty * 8 + i;
        if (row < NN) {
            float p0 = g_posagg[row * 3 + 0], p1 = g_posagg[row * 3 + 1], p2 = g_posagg[row * 3 + 2];
            float r[8];
#pragma unroll
            for (int jp = 0; jp < 4; jp++) {
                float2 v = *(float2*)&acc2[i][jp];
                r[2 * jp + 0] = v.x;
                r[2 * jp + 1] = v.y;
            }
#pragma unroll
            for (int j = 0; j < 8; j++) {
                float t = r[j] + bb[j] + p0 * wp0[j] + p1 * wp1[j] + p2 * wp2[j];
                r[j] = t; s_[j] += t; q_[j] += t * t;
            }
            *(float4*)(outp + (size_t)row * CC + tx * 8) = make_float4(r[0], r[1], r[2], r[3]);
            *(float4*)(outp + (size_t)row * CC + tx * 8 + 4) = make_float4(r[4], r[5], r[6], r[7]);
        }
    }
#pragma unroll
    for (int j = 0; j < 8; j++) {
        atomicAdd(&cs[tx * 8 + j], s_[j]);
        atomicAdd(&cq[tx * 8 + j], q_[j]);
    }
    __syncthreads();
    if (tid < 128) {
        atomicAdd(&g_sum[tid], (double)cs[tid]);
        atomicAdd(&g_sumsq[tid], (double)cq[tid]);
    }
}

// ---------------- BatchNorm finalize (separate tiny kernel; R10 proven) ----------
__global__ void k_bnfin(const float* __restrict__ g, const float* __restrict__ be) {
    int c = threadIdx.x;
    float mu = (float)(g_sum[c] / NN);
    float var = (float)(g_sumsq[c] / NN) - mu * mu;
    float sc = g[c] * rsqrtf(var + EPSV);
    g_scale[c] = sc;
    g_shift[c] = be[c] - mu * sc;
    g_sum[c] = 0.0;
    g_sumsq[c] = 0.0;
}

// layer 1: BN+ReLU + score key + MIS node-state init (warp per node)
__global__ void __launch_bounds__(256) k_bnrelu_key(const float* __restrict__ ws) {
    int gt = blockIdx.x * 256 + threadIdx.x;
    int node = gt >> 5, lane = gt & 31;
    if (node >= NN) return;
    int c = lane * 4;
    float4 v = bn4(*(float4*)(g_h1 + (size_t)node * CC + c), c);
    *(float4*)(g_h1 + (size_t)node * CC + c) = v;
    float4 w = *(const float4*)(ws + c);
    float p = v.x * w.x + v.y * w.y + v.z * w.z + v.w * w.w;
#pragma unroll
    for (int o = 16; o; o >>= 1) p += __shfl_xor_sync(0xFFFFFFFFu, p, o);
    if (lane == 0) {
        unsigned u = __float_as_uint(p);
        u = (u & 0x80000000u) ? ~u : (u | 0x80000000u);
        unsigned long long key = ((unsigned long long)u << 32) | (unsigned)(NN - 1 - node);
        g_key[node] = key;
        g_akey[node] = key;
        g_nmax[node] = 0ULL;
        g_nmax2[node] = 0ULL;
        g_mis[node] = 0;
        g_block[node] = 0;
        if (node == 0) { g_ecnt[0] = 0; g_ecnt[1] = 0; }
    }
}

// ---------------- software grid barrier (R10 version) ----------------
__device__ __forceinline__ void gbar(int nb, int& epoch) {
    __syncthreads();
    if (threadIdx.x == 0) {
        __threadfence();
        if (atomicAdd(&g_barcnt, 1) == nb - 1) {
            atomicExch(&g_barcnt, 0);
            __threadfence();
            atomicExch(&g_barrel, epoch + 1);
        } else {
            while (atomicAdd(&g_barrel, 0) < epoch + 1) __nanosleep(32);
        }
        __threadfence();
    }
    __syncthreads();
    epoch++;
}

// warp-aggregated append; ALL 32 lanes must call (full-mask ballot)
__device__ __forceinline__ void wappend(bool pred, int2 p, int2* outl, int* outc, int lane) {
    unsigned mask = __ballot_sync(0xFFFFFFFFu, pred);
    if (pred) {
        int leader = __ffs(mask) - 1;
        int base = 0;
        if (lane == leader) base = atomicAdd(outc, __popc(mask));
        base = __shfl_sync(mask, base, leader);
        outl[base + __popc(mask & ((1u << lane) - 1))] = p;
    }
}

// ---------------- fused persistent MIS (R10 version, proven) ----------------
__global__ void __launch_bounds__(512) k_mis_fused(const int* __restrict__ src,
                                                   const int* __restrict__ dst) {
    const int nb = gridDim.x;
    const int nt = nb * 512;
    const int gt = blockIdx.x * 512 + threadIdx.x;
    const int lane = threadIdx.x & 31;
    __shared__ int s_cnt, s_ep;
    if (threadIdx.x == 0) s_ep = atomicAdd(&g_barrel, 0);
    __syncthreads();
    int epoch = s_ep;

    for (int e = gt; e < EE; e += nt) {
        int s = src[e], d = dst[e];
        if (s == d) { g_block[s] = 1; continue; }
        atomicMax(&g_nmax[d], g_key[s]);
        atomicMax(&g_nmax[s], g_key[d]);
    }
    gbar(nb, epoch);
    for (int e = gt; e < EE; e += nt) {
        int s = src[e], d = dst[e];
        if (s == d) continue;
        if (!g_block[s] && g_akey[s] > g_nmax[s]) { g_mis[s] = 1; g_akey[d] = 0; }
        if (!g_block[d] && g_akey[d] > g_nmax[d]) { g_mis[d] = 1; g_akey[s] = 0; }
    }
    gbar(nb, epoch);

    int prev = EE + 1;
    unsigned long long* nmaxLast = g_nmax;
    for (int t = 1; t < MIS_ITERS; t++) {
        int ob = t & 1;
        unsigned long long* nmaxC = ob ? g_nmax2 : g_nmax;
        unsigned long long* nmaxN = ob ? g_nmax : g_nmax2;
        int2* outl = ob ? g_elB : g_elA;
        int* outc = &g_ecnt[ob];
        if (t == 1) {
            for (int e = gt; e - lane < EE; e += nt) {
                bool in = e < EE;
                int2 p = make_int2(0, 0);
                bool live = false;
                if (in) {
                    p.x = src[e]; p.y = dst[e];
                    if (p.x != p.y) {
                        unsigned long long ks = g_akey[p.x], kd = g_akey[p.y];
                        if (ks && kd && !g_mis[p.x] && !g_mis[p.y]) {
                            live = true;
                            atomicMax(&nmaxC[p.y], ks);
                            atomicMax(&nmaxC[p.x], kd);
                        }
                    }
                }
                wappend(live, p, outl, outc, lane);
            }
        } else {
            const int2* inl = ob ? g_elA : g_elB;
            int cin = g_ecnt[1 - ob];
            for (int e = gt; e - lane < cin; e += nt) {
                bool in = e < cin;
                int2 p = make_int2(0, 0);
                bool live = false;
                if (in) {
                    p = inl[e];
                    unsigned long long ks = g_akey[p.x], kd = g_akey[p.y];
                    if (ks && kd && !g_mis[p.x] && !g_mis[p.y]) {
                        live = true;
                        atomicMax(&nmaxC[p.y], ks);
                        atomicMax(&nmaxC[p.x], kd);
                    }
                }
                wappend(live, p, outl, outc, lane);
            }
        }
        gbar(nb, epoch);
        if (threadIdx.x == 0) s_cnt = g_ecnt[ob];
        __syncthreads();
        int cnt = s_cnt;
        nmaxLast = nmaxC;
        if (cnt == 0 || cnt == prev) break;
        prev = cnt;
        if (gt == 0) g_ecnt[1 - ob] = 0;
        for (int e = gt; e < cnt; e += nt) {
            int2 p = outl[e];
            if (!g_block[p.x] && g_akey[p.x] > nmaxC[p.x]) { g_mis[p.x] = 1; g_akey[p.y] = 0; }
            if (!g_block[p.y] && g_akey[p.y] > nmaxC[p.y]) { g_mis[p.y] = 1; g_akey[p.x] = 0; }
        }
        for (int i = gt; i < NN; i += nt) nmaxN[i] = 0ULL;
        gbar(nb, epoch);
    }

    for (int i = gt; i < NN; i += nt) {
        bool iso = g_akey[i] && !g_mis[i] && !g_block[i] && (nmaxLast[i] == 0ULL);
        if (iso) g_mis[i] = 1;
        g_nmax[i] = 0ULL;
    }
    gbar(nb, epoch);
    for (int e = gt; e < EE; e += nt) {
        int s = src[e], d = dst[e];
        if (g_mis[s]) atomicMax(&g_nmax[d], g_key[s]);
        if (g_mis[d]) atomicMax(&g_nmax[s], g_key[d]);
    }
}

// ---------------- pool (R10 version: decode inline) ----------------
__global__ void __launch_bounds__(256) k_pool(float* __restrict__ out) {
    int gt = blockIdx.x * 256 + threadIdx.x;
    int node = gt >> 5, lane = gt & 31;
    if (node >= NN) return;
    int cl;
    if (g_mis[node]) cl = node;
    else {
        unsigned long long b = g_nmax[node];
        cl = b ? (NN - 1 - (int)(unsigned)(b & 0xFFFFFFFFULL)) : node;
    }
    if (lane == 0) g_cluster[node] = cl;
    if (!g_mis[cl]) return;
    float4 v = *(const float4*)(g_h1 + (size_t)node * CC + lane * 4);
    int* p = (int*)(out + (size_t)cl * CC + lane * 4);
    atomicMax(p + 0, __float_as_int(v.x));
    atomicMax(p + 1, __float_as_int(v.y));
    atomicMax(p + 2, __float_as_int(v.z));
    atomicMax(p + 3, __float_as_int(v.w));
}

// tail: only the MIS-dependent regions (cluster edges, pos mask, mis flags)
__global__ void k_out_tail(float* __restrict__ out, const int* __restrict__ src,
                           const int* __restrict__ dst, const float* __restrict__ pos,
                           int out_size) {
    const int O1 = NN * CC;
    int stride = gridDim.x * blockDim.x;
    // cluster[src] and cluster[dst]: t in [0, 2*EE)
    for (int t = blockIdx.x * blockDim.x + threadIdx.x; t < 2 * EE; t += stride) {
        int o = O1 + t;
        if (o >= out_size) break;
        int node = (t < EE) ? src[t] : dst[t - EE];
        out[o] = (float)g_cluster[node];
    }
    // pos mask [3EE, 3EE+3NN) and mis flags [3EE+4NN, 3EE+5NN)
    for (int t = blockIdx.x * blockDim.x + threadIdx.x; t < 4 * NN; t += stride) {
        if (t < 3 * NN) {
            int o = O1 + 3 * EE + t;
            if (o < out_size) out[o] = g_mis[t / 3] ? pos[t] : 0.f;
        } else {
            int j = t - 3 * NN;
            int o = O1 + 3 * EE + 4 * NN + j;
            if (o < out_size) out[o] = g_mis[j] ? 1.f : 0.f;
        }
    }
}

// ---------------- launch ----------------
extern "C" void kernel_launch(void* const* d_in, const int* in_sizes, int n_in,
                              void* d_out, int out_size) {
    const float* x   = (const float*)d_in[0];
    const int*   ei  = (const int*)d_in[1];
    const float* ew  = (const float*)d_in[2];
    const float* pos = (const float*)d_in[3];
    const float* Wr0 = (const float*)d_in[5];
    const float* Wm0 = (const float*)d_in[6];
    const float* Wp0 = (const float*)d_in[7];
    const float* b0  = (const float*)d_in[8];
    const float* g0  = (const float*)d_in[9];
    const float* be0 = (const float*)d_in[10];
    const float* Wr1 = (const float*)d_in[11];
    const float* Wm1 = (const float*)d_in[12];
    const float* Wp1 = (const float*)d_in[13];
    const float* b1  = (const float*)d_in[14];
    const float* g1  = (const float*)d_in[15];
    const float* be1 = (const float*)d_in[16];
    const float* wsc = (const float*)d_in[17];
    float* out = (float*)d_out;

    const int E = in_sizes[1] / 2;
    const int* src = ei;
    const int* dst = ei + E;
    (void)E;

    int sms = 148;
    cudaDeviceGetAttribute(&sms, cudaDevAttrMultiProcessorCount, 0);

    const int EB    = (EE + 255) / 256;
    const int NWARP = (NN * 32 + 255) / 256;
    const int GGRID = (NN + 127) / 128;

    // ---- CSR build + independent out-prep (zero/ew/batch folded into hist) ----
    k_hist<<<EB, 256>>>(dst, out, ew, out_size);
    k_scan<<<1, 1024>>>();
    k_scatter<<<EB, 256>>>(src, dst, ew);

    // ---- layer 0 ----
    k_spmm_pull<<<NWARP, 256>>>(x, pos, 0);
    k_gemm<<<GGRID, 256>>>(x, Wr0, Wm0, Wp0, b0, 0, 0);
    k_bnfin<<<1, 128>>>(g0, be0);

    // ---- layer 1 ----
    k_spmm_pull<<<NWARP, 256>>>(nullptr, nullptr, 1);
    k_gemm<<<GGRID, 256>>>(nullptr, Wr1, Wm1, Wp1, b1, 1, 1);
    k_bnfin<<<1, 128>>>(g1, be1);
    k_bnrelu_key<<<NWARP, 256>>>(wsc);

    // ---- fused persistent MIS + best-neighbor ----
    k_mis_fused<<<sms, 512>>>(src, dst);

    // ---- pool (writes into pre-zeroed out), then MIS-dependent tail ----
    k_pool<<<NWARP, 256>>>(out);
    k_out_tail<<<2048, 256>>>(out, src, dst, pos, out_size);
}

// round 14
// speedup vs baseline: 1.0432x; 1.0346x over previous
#include <cuda_runtime.h>
#include <stdint.h>

#define NN 100000
#define CC 128
#define EE 1600000
#define EPSV 1e-5f
#define MIS_ITERS 32

// ---------------- scratch (device globals; no allocation) ----------------
__device__ float g_agg[NN * CC];
__device__ float g_h0[NN * CC];
__device__ float g_h1[NN * CC];
__device__ float g_posagg[NN * 3];
__device__ int g_deg[NN];
__device__ int g_rowptr[NN + 1];
__device__ int g_cursor[NN];
__device__ int g_col[EE];
__device__ float g_wgt[EE];
__device__ unsigned long long g_key[NN];
__device__ unsigned long long g_akey[NN];
__device__ unsigned long long g_nmax[NN];
__device__ unsigned long long g_nmax2[NN];
__device__ unsigned char g_block[NN];
__device__ unsigned char g_mis[NN];
__device__ int g_cluster[NN];
__device__ int2 g_elA[EE];
__device__ int2 g_elB[EE];
__device__ int g_ecnt[2];
__device__ double g_sum[CC];
__device__ double g_sumsq[CC];
__device__ float g_scale[CC];
__device__ float g_shift[CC];
__device__ int g_barcnt;
__device__ int g_barrel;

// ---------------- CSR build ----------------
__global__ void k_zero_deg() {
    int t = blockIdx.x * blockDim.x + threadIdx.x;
    if (t < NN) g_deg[t] = 0;
}

__global__ void k_hist(const int* __restrict__ dst) {
    int e = blockIdx.x * blockDim.x + threadIdx.x;
    if (e < EE) atomicAdd(&g_deg[dst[e]], 1);
}

__global__ void __launch_bounds__(1024) k_scan() {
    __shared__ int part[1024];
    int tid = threadIdx.x;
    const int CH = (NN + 1023) / 1024;
    int base = tid * CH;
    int sum = 0;
    for (int i = 0; i < CH; i++) {
        int idx = base + i;
        if (idx < NN) sum += g_deg[idx];
    }
    part[tid] = sum;
    __syncthreads();
    for (int off = 1; off < 1024; off <<= 1) {
        int v = (tid >= off) ? part[tid - off] : 0;
        __syncthreads();
        part[tid] += v;
        __syncthreads();
    }
    int run = (tid == 0) ? 0 : part[tid - 1];
    for (int i = 0; i < CH; i++) {
        int idx = base + i;
        if (idx < NN) {
            g_rowptr[idx] = run;
            g_cursor[idx] = run;
            run += g_deg[idx];
        }
    }
    if (tid == 1023) g_rowptr[NN] = run;
}

__global__ void k_scatter(const int* __restrict__ src, const int* __restrict__ dst,
                          const float* __restrict__ ew) {
    int e = blockIdx.x * blockDim.x + threadIdx.x;
    if (e >= EE) return;
    int d = dst[e];
    int idx = atomicAdd(&g_cursor[d], 1);
    g_col[idx] = src[e];
    g_wgt[idx] = ew[e];
}

// ---------------- BN apply helpers ----------------
__device__ __forceinline__ float4 bn4s(float4 v, float4 sc, float4 sh) {
    v.x = fmaxf(fmaf(v.x, sc.x, sh.x), 0.f);
    v.y = fmaxf(fmaf(v.y, sc.y, sh.y), 0.f);
    v.z = fmaxf(fmaf(v.z, sc.z, sh.z), 0.f);
    v.w = fmaxf(fmaf(v.w, sc.w, sh.w), 0.f);
    return v;
}
__device__ __forceinline__ float4 bn4(float4 v, int ch) {
    return bn4s(v, *(const float4*)(g_scale + ch), *(const float4*)(g_shift + ch));
}

// ---------------- pull-SpMM (simple loop; TLP hides L2 latency) ------------
__global__ void __launch_bounds__(256) k_spmm_pull(const float* __restrict__ xin,
                                                   const float* __restrict__ pos,
                                                   int bn) {
    const float* x = xin ? xin : g_h0;
    int gt = blockIdx.x * 256 + threadIdx.x;
    int node = gt >> 5, lane = gt & 31;
    if (node >= NN) return;
    int e0 = g_rowptr[node], e1 = g_rowptr[node + 1];
    float4 sc = make_float4(0.f, 0.f, 0.f, 0.f), sh = sc;
    if (bn) { sc = *(const float4*)(g_scale + lane * 4); sh = *(const float4*)(g_shift + lane * 4); }
    float4 acc = make_float4(0.f, 0.f, 0.f, 0.f);
    bool dopos = (pos != nullptr) && (lane < 3);
    float pacc = 0.f;
    float pd = dopos ? pos[node * 3 + lane] : 0.f;
    int scur = 0; float wcur = 0.f;
    if (e0 < e1) { scur = g_col[e0]; wcur = g_wgt[e0]; }
    for (int e = e0; e < e1; e++) {
        int snx = 0; float wnx = 0.f;
        if (e + 1 < e1) { snx = g_col[e + 1]; wnx = g_wgt[e + 1]; }
        float4 v = *(const float4*)(x + (size_t)scur * CC + lane * 4);
        if (bn) v = bn4s(v, sc, sh);
        acc.x += wcur * v.x; acc.y += wcur * v.y;
        acc.z += wcur * v.z; acc.w += wcur * v.w;
        if (dopos) pacc += wcur * (pos[scur * 3 + lane] - pd);
        scur = snx; wcur = wnx;
    }
    *(float4*)(g_agg + (size_t)node * CC + lane * 4) = acc;
    if (dopos) g_posagg[node * 3 + lane] = pacc;
}

// ---------------- double-buffered fused GEMM + BN stats (f32x2 packed FMA) -------
__global__ void __launch_bounds__(256, 2) k_gemm(const float* __restrict__ Xin,
                                                 const float* __restrict__ Wr,
                                                 const float* __restrict__ Wm,
                                                 const float* __restrict__ Wp,
                                                 const float* __restrict__ bias,
                                                 int outsel, int bnA) {
    __shared__ __align__(16) float As[2][8][128];
    __shared__ __align__(16) float Bs[2][8][128];
    __shared__ float cs[128], cq[128];
    const float* X = Xin ? Xin : g_h0;
    float* outp = outsel ? g_h1 : g_h0;
    int bm = blockIdx.x * 128;
    int tid = threadIdx.x;
    if (tid < 128) { cs[tid] = 0.f; cq[tid] = 0.f; }
    int tx = tid & 15, ty = tid >> 4;
    int am = tid >> 1, ak = (tid & 1) * 4;
    int kb = tid >> 5, bc = (tid & 31) * 4;
    int arow = bm + am;
    bool aval = arow < NN;

    unsigned long long acc2[8][4];
#pragma unroll
    for (int i = 0; i < 8; i++)
#pragma unroll
        for (int jp = 0; jp < 4; jp++) acc2[i][jp] = 0ULL;

    float4 areg;
    {
        const float* gp = Wr + (size_t)kb * CC + bc;
        unsigned sa = (unsigned)__cvta_generic_to_shared(&Bs[0][kb][bc]);
        asm volatile("cp.async.ca.shared.global [%0], [%1], 16;" :: "r"(sa), "l"(gp));
        asm volatile("cp.async.commit_group;");
        areg = make_float4(0.f, 0.f, 0.f, 0.f);
        if (aval) {
            areg = *(const float4*)(X + (size_t)arow * CC + ak);
            if (bnA) areg = bn4(areg, ak);
        }
        As[0][ak + 0][am] = areg.x; As[0][ak + 1][am] = areg.y;
        As[0][ak + 2][am] = areg.z; As[0][ak + 3][am] = areg.w;
        asm volatile("cp.async.wait_group 0;");
    }
    __syncthreads();

    for (int kt = 0; kt < 256; kt += 8) {
        int s = (kt >> 3) & 1;
        bool more = (kt + 8) < 256;
        if (more) {
            int kn = kt + 8;
            const float* SB = (kn < 128) ? Wr : Wm;
            const float* gp = SB + (size_t)((kn + kb) & 127) * CC + bc;
            unsigned sa = (unsigned)__cvta_generic_to_shared(&Bs[s ^ 1][kb][bc]);
            asm volatile("cp.async.ca.shared.global [%0], [%1], 16;" :: "r"(sa), "l"(gp));
            asm volatile("cp.async.commit_group;");
            areg = make_float4(0.f, 0.f, 0.f, 0.f);
            if (aval) {
                const float* SA = (kn < 128) ? X : g_agg;
                areg = *(const float4*)(SA + (size_t)arow * CC + ((kn + ak) & 127));
                if (bnA && kn < 128) areg = bn4(areg, kn + ak);
            }
        }
#pragma unroll
        for (int k = 0; k < 8; k++) {
            float a[8];
            *(float4*)&a[0] = *(const float4*)&As[s][k][ty * 8];
            *(float4*)&a[4] = *(const float4*)&As[s][k][ty * 8 + 4];
            ulonglong2 b01 = *(const ulonglong2*)&Bs[s][k][tx * 8];
            ulonglong2 b23 = *(const ulonglong2*)&Bs[s][k][tx * 8 + 4];
            unsigned long long bp0 = b01.x, bp1 = b01.y, bp2 = b23.x, bp3 = b23.y;
#pragma unroll
            for (int i = 0; i < 8; i++) {
                unsigned long long aa;
                asm("mov.b64 %0, {%1, %1};" : "=l"(aa) : "f"(a[i]));
                asm("fma.rn.f32x2 %0, %1, %2, %0;" : "+l"(acc2[i][0]) : "l"(aa), "l"(bp0));
                asm("fma.rn.f32x2 %0, %1, %2, %0;" : "+l"(acc2[i][1]) : "l"(aa), "l"(bp1));
                asm("fma.rn.f32x2 %0, %1, %2, %0;" : "+l"(acc2[i][2]) : "l"(aa), "l"(bp2));
                asm("fma.rn.f32x2 %0, %1, %2, %0;" : "+l"(acc2[i][3]) : "l"(aa), "l"(bp3));
            }
        }
        if (more) {
            As[s ^ 1][ak + 0][am] = areg.x; As[s ^ 1][ak + 1][am] = areg.y;
            As[s ^ 1][ak + 2][am] = areg.z; As[s ^ 1][ak + 3][am] = areg.w;
            asm volatile("cp.async.wait_group 0;");
        }
        __syncthreads();
    }

    float bb[8], wp0[8], wp1[8], wp2[8];
#pragma unroll
    for (int j = 0; j < 8; j++) {
        int col = tx * 8 + j;
        bb[j] = bias[col]; wp0[j] = Wp[col]; wp1[j] = Wp[CC + col]; wp2[j] = Wp[2 * CC + col];
    }
    float s_[8], q_[8];
#pragma unroll
    for (int j = 0; j < 8; j++) { s_[j] = 0.f; q_[j] = 0.f; }
#pragma unroll
    for (int i = 0; i < 8; i++) {
        int row = bm + ty * 8 + i;
        if (row < NN) {
            float p0 = g_posagg[row * 3 + 0], p1 = g_posagg[row * 3 + 1], p2 = g_posagg[row * 3 + 2];
            float r[8];
#pragma unroll
            for (int jp = 0; jp < 4; jp++) {
                float2 v = *(float2*)&acc2[i][jp];
                r[2 * jp + 0] = v.x;
                r[2 * jp + 1] = v.y;
            }
#pragma unroll
            for (int j = 0; j < 8; j++) {
                float t = r[j] + bb[j] + p0 * wp0[j] + p1 * wp1[j] + p2 * wp2[j];
                r[j] = t; s_[j] += t; q_[j] += t * t;
            }
            *(float4*)(outp + (size_t)row * CC + tx * 8) = make_float4(r[0], r[1], r[2], r[3]);
            *(float4*)(outp + (size_t)row * CC + tx * 8 + 4) = make_float4(r[4], r[5], r[6], r[7]);
        }
    }
#pragma unroll
    for (int j = 0; j < 8; j++) {
        atomicAdd(&cs[tx * 8 + j], s_[j]);
        atomicAdd(&cq[tx * 8 + j], q_[j]);
    }
    __syncthreads();
    if (tid < 128) {
        atomicAdd(&g_sum[tid], (double)cs[tid]);
        atomicAdd(&g_sumsq[tid], (double)cq[tid]);
    }
}

// ---------------- BatchNorm finalize (self-clearing stats) ----------------
__global__ void k_bnfin(const float* __restrict__ g, const float* __restrict__ be) {
    int c = threadIdx.x;
    float mu = (float)(g_sum[c] / NN);
    float var = (float)(g_sumsq[c] / NN) - mu * mu;
    float sc = g[c] * rsqrtf(var + EPSV);
    g_scale[c] = sc;
    g_shift[c] = be[c] - mu * sc;
    g_sum[c] = 0.0;
    g_sumsq[c] = 0.0;
}

// layer 1: BN+ReLU + score key + MIS node-state init (warp per node)
__global__ void __launch_bounds__(256) k_bnrelu_key(const float* __restrict__ ws) {
    int gt = blockIdx.x * 256 + threadIdx.x;
    int node = gt >> 5, lane = gt & 31;
    if (node >= NN) return;
    int c = lane * 4;
    float4 v = bn4(*(float4*)(g_h1 + (size_t)node * CC + c), c);
    *(float4*)(g_h1 + (size_t)node * CC + c) = v;
    float4 w = *(const float4*)(ws + c);
    float p = v.x * w.x + v.y * w.y + v.z * w.z + v.w * w.w;
#pragma unroll
    for (int o = 16; o; o >>= 1) p += __shfl_xor_sync(0xFFFFFFFFu, p, o);
    if (lane == 0) {
        unsigned u = __float_as_uint(p);
        u = (u & 0x80000000u) ? ~u : (u | 0x80000000u);
        unsigned long long key = ((unsigned long long)u << 32) | (unsigned)(NN - 1 - node);
        g_key[node] = key;
        g_akey[node] = key;
        g_nmax[node] = 0ULL;
        g_nmax2[node] = 0ULL;
        g_mis[node] = 0;
        g_block[node] = 0;
        if (node == 0) { g_ecnt[0] = 0; g_ecnt[1] = 0; }
    }
}

// ---------------- software grid barrier ----------------
__device__ __forceinline__ void gbar(int nb, int& epoch) {
    __syncthreads();
    if (threadIdx.x == 0) {
        __threadfence();
        if (atomicAdd(&g_barcnt, 1) == nb - 1) {
            atomicExch(&g_barcnt, 0);
            __threadfence();
            atomicExch(&g_barrel, epoch + 1);
        } else {
            while (atomicAdd(&g_barrel, 0) < epoch + 1) __nanosleep(32);
        }
        __threadfence();
    }
    __syncthreads();
    epoch++;
}

// warp-aggregated append; ALL 32 lanes must call (full-mask ballot)
__device__ __forceinline__ void wappend(bool pred, int2 p, int2* outl, int* outc, int lane) {
    unsigned mask = __ballot_sync(0xFFFFFFFFu, pred);
    if (pred) {
        int leader = __ffs(mask) - 1;
        int base = 0;
        if (lane == leader) base = atomicAdd(outc, __popc(mask));
        base = __shfl_sync(mask, base, leader);
        outl[base + __popc(mask & ((1u << lane) - 1))] = p;
    }
}

// ---------------- fused persistent MIS ----------------
__global__ void __launch_bounds__(512) k_mis_fused(const int* __restrict__ src,
                                                   const int* __restrict__ dst) {
    const int nb = gridDim.x;
    const int nt = nb * 512;
    const int gt = blockIdx.x * 512 + threadIdx.x;
    const int lane = threadIdx.x & 31;
    __shared__ int s_cnt, s_ep;
    if (threadIdx.x == 0) s_ep = atomicAdd(&g_barrel, 0);
    __syncthreads();
    int epoch = s_ep;

    for (int e = gt; e < EE; e += nt) {
        int s = src[e], d = dst[e];
        if (s == d) { g_block[s] = 1; continue; }
        atomicMax(&g_nmax[d], g_key[s]);
        atomicMax(&g_nmax[s], g_key[d]);
    }
    gbar(nb, epoch);
    for (int e = gt; e < EE; e += nt) {
        int s = src[e], d = dst[e];
        if (s == d) continue;
        if (!g_block[s] && g_akey[s] > g_nmax[s]) { g_mis[s] = 1; g_akey[d] = 0; }
        if (!g_block[d] && g_akey[d] > g_nmax[d]) { g_mis[d] = 1; g_akey[s] = 0; }
    }
    gbar(nb, epoch);

    int prev = EE + 1;
    unsigned long long* nmaxLast = g_nmax;
    for (int t = 1; t < MIS_ITERS; t++) {
        int ob = t & 1;
        unsigned long long* nmaxC = ob ? g_nmax2 : g_nmax;
        unsigned long long* nmaxN = ob ? g_nmax : g_nmax2;
        int2* outl = ob ? g_elB : g_elA;
        int* outc = &g_ecnt[ob];
        if (t == 1) {
            for (int e = gt; e - lane < EE; e += nt) {
                bool in = e < EE;
                int2 p = make_int2(0, 0);
                bool live = false;
                if (in) {
                    p.x = src[e]; p.y = dst[e];
                    if (p.x != p.y) {
                        unsigned long long ks = g_akey[p.x], kd = g_akey[p.y];
                        if (ks && kd && !g_mis[p.x] && !g_mis[p.y]) {
                            live = true;
                            atomicMax(&nmaxC[p.y], ks);
                            atomicMax(&nmaxC[p.x], kd);
                        }
                    }
                }
                wappend(live, p, outl, outc, lane);
            }
        } else {
            const int2* inl = ob ? g_elA : g_elB;
            int cin = g_ecnt[1 - ob];
            for (int e = gt; e - lane < cin; e += nt) {
                bool in = e < cin;
                int2 p = make_int2(0, 0);
                bool live = false;
                if (in) {
                    p = inl[e];
                    unsigned long long ks = g_akey[p.x], kd = g_akey[p.y];
                    if (ks && kd && !g_mis[p.x] && !g_mis[p.y]) {
                        live = true;
                        atomicMax(&nmaxC[p.y], ks);
                        atomicMax(&nmaxC[p.x], kd);
                    }
                }
                wappend(live, p, outl, outc, lane);
            }
        }
        gbar(nb, epoch);
        if (threadIdx.x == 0) s_cnt = g_ecnt[ob];
        __syncthreads();
        int cnt = s_cnt;
        nmaxLast = nmaxC;
        if (cnt == 0 || cnt == prev) break;
        prev = cnt;
        if (gt == 0) g_ecnt[1 - ob] = 0;
        for (int e = gt; e < cnt; e += nt) {
            int2 p = outl[e];
            if (!g_block[p.x] && g_akey[p.x] > nmaxC[p.x]) { g_mis[p.x] = 1; g_akey[p.y] = 0; }
            if (!g_block[p.y] && g_akey[p.y] > nmaxC[p.y]) { g_mis[p.y] = 1; g_akey[p.x] = 0; }
        }
        for (int i = gt; i < NN; i += nt) nmaxN[i] = 0ULL;
        gbar(nb, epoch);
    }

    for (int i = gt; i < NN; i += nt) {
        bool iso = g_akey[i] && !g_mis[i] && !g_block[i] && (nmaxLast[i] == 0ULL);
        if (iso) g_mis[i] = 1;
        g_nmax[i] = 0ULL;
    }
    gbar(nb, epoch);
    for (int e = gt; e < EE; e += nt) {
        int s = src[e], d = dst[e];
        if (g_mis[s]) atomicMax(&g_nmax[d], g_key[s]);
        if (g_mis[d]) atomicMax(&g_nmax[s], g_key[d]);
    }
}

// ---------------- outputs ----------------
__global__ void k_zero_out(float* __restrict__ out, int out_size) {
    int t = blockIdx.x * blockDim.x + threadIdx.x;
    if (t < NN * CC / 4 && 4 * t + 3 < out_size)
        ((float4*)out)[t] = make_float4(0.f, 0.f, 0.f, 0.f);
}

__global__ void __launch_bounds__(256) k_pool(float* __restrict__ out) {
    int gt = blockIdx.x * 256 + threadIdx.x;
    int node = gt >> 5, lane = gt & 31;
    if (node >= NN) return;
    int cl;
    if (g_mis[node]) cl = node;
    else {
        unsigned long long b = g_nmax[node];
        cl = b ? (NN - 1 - (int)(unsigned)(b & 0xFFFFFFFFULL)) : node;
    }
    if (lane == 0) g_cluster[node] = cl;
    if (!g_mis[cl]) return;
    float4 v = *(const float4*)(g_h1 + (size_t)node * CC + lane * 4);
    int* p = (int*)(out + (size_t)cl * CC + lane * 4);
    atomicMax(p + 0, __float_as_int(v.x));
    atomicMax(p + 1, __float_as_int(v.y));
    atomicMax(p + 2, __float_as_int(v.z));
    atomicMax(p + 3, __float_as_int(v.w));
}

__global__ void k_out_tail(float* __restrict__ out, const int* __restrict__ src,
                           const int* __restrict__ dst, const float* __restrict__ ew,
                           const float* __restrict__ pos, int out_size) {
    const int O1 = NN * CC;
    const int TAIL = 3 * EE + 5 * NN;
    int stride = gridDim.x * blockDim.x;
    for (int t = blockIdx.x * blockDim.x + threadIdx.x; t < TAIL; t += stride) {
        int o = O1 + t;
        if (o >= out_size) return;
        float val;
        if (t < EE) {
            val = (float)g_cluster[src[t]];
        } else if (t < 2 * EE) {
            val = (float)g_cluster[dst[t - EE]];
        } else if (t < 3 * EE) {
            val = ew[t - 2 * EE];
        } else if (t < 3 * EE + 3 * NN) {
            int j = t - 3 * EE;
            val = g_mis[j / 3] ? pos[j] : 0.f;
        } else if (t < 3 * EE + 4 * NN) {
            val = 0.f;  // batch
        } else {
            val = g_mis[t - (3 * EE + 4 * NN)] ? 1.f : 0.f;
        }
        out[o] = val;
    }
}

// ---------------- launch ----------------
extern "C" void kernel_launch(void* const* d_in, const int* in_sizes, int n_in,
                              void* d_out, int out_size) {
    const float* x   = (const float*)d_in[0];
    const int*   ei  = (const int*)d_in[1];
    const float* ew  = (const float*)d_in[2];
    const float* pos = (const float*)d_in[3];
    const float* Wr0 = (const float*)d_in[5];
    const float* Wm0 = (const float*)d_in[6];
    const float* Wp0 = (const float*)d_in[7];
    const float* b0  = (const float*)d_in[8];
    const float* g0  = (const float*)d_in[9];
    const float* be0 = (const float*)d_in[10];
    const float* Wr1 = (const float*)d_in[11];
    const float* Wm1 = (const float*)d_in[12];
    const float* Wp1 = (const float*)d_in[13];
    const float* b1  = (const float*)d_in[14];
    const float* g1  = (const float*)d_in[15];
    const float* be1 = (const float*)d_in[16];
    const float* wsc = (const float*)d_in[17];
    float* out = (float*)d_out;

    const int E = in_sizes[1] / 2;
    const int* src = ei;
    const int* dst = ei + E;
    (void)E;

    int sms = 148;
    cudaDeviceGetAttribute(&sms, cudaDevAttrMultiProcessorCount, 0);

    const int NB4   = (NN * CC / 4 + 255) / 256;
    const int EB    = (EE + 255) / 256;
    const int NWARP = (NN * 32 + 255) / 256;
    const int NBn   = (NN + 255) / 256;
    const int GGRID = (NN + 127) / 128;

    // ---- CSR build ----
    k_zero_deg<<<NBn, 256>>>();
    k_hist<<<EB, 256>>>(dst);
    k_scan<<<1, 1024>>>();
    k_scatter<<<EB, 256>>>(src, dst, ew);

    // ---- layer 0 ----
    k_spmm_pull<<<NWARP, 256>>>(x, pos, 0);
    k_gemm<<<GGRID, 256>>>(x, Wr0, Wm0, Wp0, b0, 0, 0);
    k_bnfin<<<1, 128>>>(g0, be0);

    // ---- layer 1 ----
    k_spmm_pull<<<NWARP, 256>>>(nullptr, nullptr, 1);
    k_gemm<<<GGRID, 256>>>(nullptr, Wr1, Wm1, Wp1, b1, 1, 1);
    k_bnfin<<<1, 128>>>(g1, be1);
    k_bnrelu_key<<<NWARP, 256>>>(wsc);

    // ---- fused persistent MIS + best-neighbor ----
    k_mis_fused<<<sms, 512>>>(src, dst);

    // ---- pooling + outputs ----
    k_zero_out<<<NB4, 256>>>(out, out_size);
    k_pool<<<NWARP, 256>>>(out);
    k_out_tail<<<2048, 256>>>(out, src, dst, ew, pos, out_size);
}

// round 15
// speedup vs baseline: 1.0587x; 1.0148x over previous
#include <cuda_runtime.h>
#include <stdint.h>

#define NN 100000
#define CC 128
#define EE 1600000
#define EPSV 1e-5f
#define MIS_ITERS 32

// ---------------- scratch (device globals; no allocation) ----------------
__device__ float g_agg[NN * CC];
__device__ float g_h0[NN * CC];
__device__ float g_h1[NN * CC];
__device__ float g_posagg[NN * 3];
__device__ int g_deg[NN];
__device__ int g_rowptr[NN + 1];
__device__ int g_cursor[NN];
__device__ int g_col[EE];
__device__ float g_wgt[EE];
__device__ unsigned long long g_key[NN];
__device__ unsigned long long g_akey[NN];
__device__ unsigned long long g_nmax[NN];
__device__ unsigned long long g_nmax2[NN];
__device__ unsigned char g_block[NN];
__device__ unsigned char g_mis[NN];
__device__ int g_cluster[NN];
__device__ int2 g_elA[EE];
__device__ int2 g_elB[EE];
__device__ int g_ecnt[2];
__device__ double g_sum[CC];
__device__ double g_sumsq[CC];
__device__ float g_scale[CC];
__device__ float g_shift[CC];
__device__ int g_barcnt;
__device__ int g_barrel;

// ---------------- CSR build (R10 verbatim) ----------------
__global__ void k_zero_deg() {
    int t = blockIdx.x * blockDim.x + threadIdx.x;
    if (t < NN) g_deg[t] = 0;
}

__global__ void k_hist(const int* __restrict__ dst) {
    int e = blockIdx.x * blockDim.x + threadIdx.x;
    if (e < EE) atomicAdd(&g_deg[dst[e]], 1);
}

__global__ void __launch_bounds__(1024) k_scan() {
    __shared__ int part[1024];
    int tid = threadIdx.x;
    const int CH = (NN + 1023) / 1024;
    int base = tid * CH;
    int sum = 0;
    for (int i = 0; i < CH; i++) {
        int idx = base + i;
        if (idx < NN) sum += g_deg[idx];
    }
    part[tid] = sum;
    __syncthreads();
    for (int off = 1; off < 1024; off <<= 1) {
        int v = (tid >= off) ? part[tid - off] : 0;
        __syncthreads();
        part[tid] += v;
        __syncthreads();
    }
    int run = (tid == 0) ? 0 : part[tid - 1];
    for (int i = 0; i < CH; i++) {
        int idx = base + i;
        if (idx < NN) {
            g_rowptr[idx] = run;
            g_cursor[idx] = run;
            run += g_deg[idx];
        }
    }
    if (tid == 1023) g_rowptr[NN] = run;
}

__global__ void k_scatter(const int* __restrict__ src, const int* __restrict__ dst,
                          const float* __restrict__ ew) {
    int e = blockIdx.x * blockDim.x + threadIdx.x;
    if (e >= EE) return;
    int d = dst[e];
    int idx = atomicAdd(&g_cursor[d], 1);
    g_col[idx] = src[e];
    g_wgt[idx] = ew[e];
}

// ---------------- BN apply helpers ----------------
__device__ __forceinline__ float4 bn4s(float4 v, float4 sc, float4 sh) {
    v.x = fmaxf(fmaf(v.x, sc.x, sh.x), 0.f);
    v.y = fmaxf(fmaf(v.y, sc.y, sh.y), 0.f);
    v.z = fmaxf(fmaf(v.z, sc.z, sh.z), 0.f);
    v.w = fmaxf(fmaf(v.w, sc.w, sh.w), 0.f);
    return v;
}
__device__ __forceinline__ float4 bn4(float4 v, int ch) {
    return bn4s(v, *(const float4*)(g_scale + ch), *(const float4*)(g_shift + ch));
}

// ---------------- pull-SpMM (R10 verbatim) ----------------
__global__ void __launch_bounds__(256) k_spmm_pull(const float* __restrict__ xin,
                                                   const float* __restrict__ pos,
                                                   int bn) {
    const float* x = xin ? xin : g_h0;
    int gt = blockIdx.x * 256 + threadIdx.x;
    int node = gt >> 5, lane = gt & 31;
    if (node >= NN) return;
    int e0 = g_rowptr[node], e1 = g_rowptr[node + 1];
    float4 sc = make_float4(0.f, 0.f, 0.f, 0.f), sh = sc;
    if (bn) { sc = *(const float4*)(g_scale + lane * 4); sh = *(const float4*)(g_shift + lane * 4); }
    float4 acc = make_float4(0.f, 0.f, 0.f, 0.f);
    bool dopos = (pos != nullptr) && (lane < 3);
    float pacc = 0.f;
    float pd = dopos ? pos[node * 3 + lane] : 0.f;
    int scur = 0; float wcur = 0.f;
    if (e0 < e1) { scur = g_col[e0]; wcur = g_wgt[e0]; }
    for (int e = e0; e < e1; e++) {
        int snx = 0; float wnx = 0.f;
        if (e + 1 < e1) { snx = g_col[e + 1]; wnx = g_wgt[e + 1]; }
        float4 v = *(const float4*)(x + (size_t)scur * CC + lane * 4);
        if (bn) v = bn4s(v, sc, sh);
        acc.x += wcur * v.x; acc.y += wcur * v.y;
        acc.z += wcur * v.z; acc.w += wcur * v.w;
        if (dopos) pacc += wcur * (pos[scur * 3 + lane] - pd);
        scur = snx; wcur = wnx;
    }
    *(float4*)(g_agg + (size_t)node * CC + lane * 4) = acc;
    if (dopos) g_posagg[node * 3 + lane] = pacc;
}

// ---------------- double-buffered fused GEMM + BN stats (f32x2; R10 verbatim) ----
__global__ void __launch_bounds__(256, 2) k_gemm(const float* __restrict__ Xin,
                                                 const float* __restrict__ Wr,
                                                 const float* __restrict__ Wm,
                                                 const float* __restrict__ Wp,
                                                 const float* __restrict__ bias,
                                                 int outsel, int bnA) {
    __shared__ __align__(16) float As[2][8][128];
    __shared__ __align__(16) float Bs[2][8][128];
    __shared__ float cs[128], cq[128];
    const float* X = Xin ? Xin : g_h0;
    float* outp = outsel ? g_h1 : g_h0;
    int bm = blockIdx.x * 128;
    int tid = threadIdx.x;
    if (tid < 128) { cs[tid] = 0.f; cq[tid] = 0.f; }
    int tx = tid & 15, ty = tid >> 4;
    int am = tid >> 1, ak = (tid & 1) * 4;
    int kb = tid >> 5, bc = (tid & 31) * 4;
    int arow = bm + am;
    bool aval = arow < NN;

    unsigned long long acc2[8][4];
#pragma unroll
    for (int i = 0; i < 8; i++)
#pragma unroll
        for (int jp = 0; jp < 4; jp++) acc2[i][jp] = 0ULL;

    float4 areg;
    {
        const float* gp = Wr + (size_t)kb * CC + bc;
        unsigned sa = (unsigned)__cvta_generic_to_shared(&Bs[0][kb][bc]);
        asm volatile("cp.async.ca.shared.global [%0], [%1], 16;" :: "r"(sa), "l"(gp));
        asm volatile("cp.async.commit_group;");
        areg = make_float4(0.f, 0.f, 0.f, 0.f);
        if (aval) {
            areg = *(const float4*)(X + (size_t)arow * CC + ak);
            if (bnA) areg = bn4(areg, ak);
        }
        As[0][ak + 0][am] = areg.x; As[0][ak + 1][am] = areg.y;
        As[0][ak + 2][am] = areg.z; As[0][ak + 3][am] = areg.w;
        asm volatile("cp.async.wait_group 0;");
    }
    __syncthreads();

    for (int kt = 0; kt < 256; kt += 8) {
        int s = (kt >> 3) & 1;
        bool more = (kt + 8) < 256;
        if (more) {
            int kn = kt + 8;
            const float* SB = (kn < 128) ? Wr : Wm;
            const float* gp = SB + (size_t)((kn + kb) & 127) * CC + bc;
            unsigned sa = (unsigned)__cvta_generic_to_shared(&Bs[s ^ 1][kb][bc]);
            asm volatile("cp.async.ca.shared.global [%0], [%1], 16;" :: "r"(sa), "l"(gp));
            asm volatile("cp.async.commit_group;");
            areg = make_float4(0.f, 0.f, 0.f, 0.f);
            if (aval) {
                const float* SA = (kn < 128) ? X : g_agg;
                areg = *(const float4*)(SA + (size_t)arow * CC + ((kn + ak) & 127));
                if (bnA && kn < 128) areg = bn4(areg, kn + ak);
            }
        }
#pragma unroll
        for (int k = 0; k < 8; k++) {
            float a[8];
            *(float4*)&a[0] = *(const float4*)&As[s][k][ty * 8];
            *(float4*)&a[4] = *(const float4*)&As[s][k][ty * 8 + 4];
            ulonglong2 b01 = *(const ulonglong2*)&Bs[s][k][tx * 8];
            ulonglong2 b23 = *(const ulonglong2*)&Bs[s][k][tx * 8 + 4];
            unsigned long long bp0 = b01.x, bp1 = b01.y, bp2 = b23.x, bp3 = b23.y;
#pragma unroll
            for (int i = 0; i < 8; i++) {
                unsigned long long aa;
                asm("mov.b64 %0, {%1, %1};" : "=l"(aa) : "f"(a[i]));
                asm("fma.rn.f32x2 %0, %1, %2, %0;" : "+l"(acc2[i][0]) : "l"(aa), "l"(bp0));
                asm("fma.rn.f32x2 %0, %1, %2, %0;" : "+l"(acc2[i][1]) : "l"(aa), "l"(bp1));
                asm("fma.rn.f32x2 %0, %1, %2, %0;" : "+l"(acc2[i][2]) : "l"(aa), "l"(bp2));
                asm("fma.rn.f32x2 %0, %1, %2, %0;" : "+l"(acc2[i][3]) : "l"(aa), "l"(bp3));
            }
        }
        if (more) {
            As[s ^ 1][ak + 0][am] = areg.x; As[s ^ 1][ak + 1][am] = areg.y;
            As[s ^ 1][ak + 2][am] = areg.z; As[s ^ 1][ak + 3][am] = areg.w;
            asm volatile("cp.async.wait_group 0;");
        }
        __syncthreads();
    }

    float bb[8], wp0[8], wp1[8], wp2[8];
#pragma unroll
    for (int j = 0; j < 8; j++) {
        int col = tx * 8 + j;
        bb[j] = bias[col]; wp0[j] = Wp[col]; wp1[j] = Wp[CC + col]; wp2[j] = Wp[2 * CC + col];
    }
    float s_[8], q_[8];
#pragma unroll
    for (int j = 0; j < 8; j++) { s_[j] = 0.f; q_[j] = 0.f; }
#pragma unroll
    for (int i = 0; i < 8; i++) {
        int row = bm + ty * 8 + i;
        if (row < NN) {
            float p0 = g_posagg[row * 3 + 0], p1 = g_posagg[row * 3 + 1], p2 = g_posagg[row * 3 + 2];
            float r[8];
#pragma unroll
            for (int jp = 0; jp < 4; jp++) {
                float2 v = *(float2*)&acc2[i][jp];
                r[2 * jp + 0] = v.x;
                r[2 * jp + 1] = v.y;
            }
#pragma unroll
            for (int j = 0; j < 8; j++) {
                float t = r[j] + bb[j] + p0 * wp0[j] + p1 * wp1[j] + p2 * wp2[j];
                r[j] = t; s_[j] += t; q_[j] += t * t;
            }
            *(float4*)(outp + (size_t)row * CC + tx * 8) = make_float4(r[0], r[1], r[2], r[3]);
            *(float4*)(outp + (size_t)row * CC + tx * 8 + 4) = make_float4(r[4], r[5], r[6], r[7]);
        }
    }
#pragma unroll
    for (int j = 0; j < 8; j++) {
        atomicAdd(&cs[tx * 8 + j], s_[j]);
        atomicAdd(&cq[tx * 8 + j], q_[j]);
    }
    __syncthreads();
    if (tid < 128) {
        atomicAdd(&g_sum[tid], (double)cs[tid]);
        atomicAdd(&g_sumsq[tid], (double)cq[tid]);
    }
}

// ---------------- BatchNorm finalize (R10 verbatim) ----------------
__global__ void k_bnfin(const float* __restrict__ g, const float* __restrict__ be) {
    int c = threadIdx.x;
    float mu = (float)(g_sum[c] / NN);
    float var = (float)(g_sumsq[c] / NN) - mu * mu;
    float sc = g[c] * rsqrtf(var + EPSV);
    g_scale[c] = sc;
    g_shift[c] = be[c] - mu * sc;
    g_sum[c] = 0.0;
    g_sumsq[c] = 0.0;
}

// layer 1: BN+ReLU + score key + MIS node-state init (R10 verbatim)
__global__ void __launch_bounds__(256) k_bnrelu_key(const float* __restrict__ ws) {
    int gt = blockIdx.x * 256 + threadIdx.x;
    int node = gt >> 5, lane = gt & 31;
    if (node >= NN) return;
    int c = lane * 4;
    float4 v = bn4(*(float4*)(g_h1 + (size_t)node * CC + c), c);
    *(float4*)(g_h1 + (size_t)node * CC + c) = v;
    float4 w = *(const float4*)(ws + c);
    float p = v.x * w.x + v.y * w.y + v.z * w.z + v.w * w.w;
#pragma unroll
    for (int o = 16; o; o >>= 1) p += __shfl_xor_sync(0xFFFFFFFFu, p, o);
    if (lane == 0) {
        unsigned u = __float_as_uint(p);
        u = (u & 0x80000000u) ? ~u : (u | 0x80000000u);
        unsigned long long key = ((unsigned long long)u << 32) | (unsigned)(NN - 1 - node);
        g_key[node] = key;
        g_akey[node] = key;
        g_nmax[node] = 0ULL;
        g_nmax2[node] = 0ULL;
        g_mis[node] = 0;
        g_block[node] = 0;
        if (node == 0) { g_ecnt[0] = 0; g_ecnt[1] = 0; }
    }
}

// ---------------- software grid barrier (R10 verbatim) ----------------
__device__ __forceinline__ void gbar(int nb, int& epoch) {
    __syncthreads();
    if (threadIdx.x == 0) {
        __threadfence();
        if (atomicAdd(&g_barcnt, 1) == nb - 1) {
            atomicExch(&g_barcnt, 0);
            __threadfence();
            atomicExch(&g_barrel, epoch + 1);
        } else {
            while (atomicAdd(&g_barrel, 0) < epoch + 1) __nanosleep(32);
        }
        __threadfence();
    }
    __syncthreads();
    epoch++;
}

// warp-aggregated append; ALL 32 lanes must call (full-mask ballot)
__device__ __forceinline__ void wappend(bool pred, int2 p, int2* outl, int* outc, int lane) {
    unsigned mask = __ballot_sync(0xFFFFFFFFu, pred);
    if (pred) {
        int leader = __ffs(mask) - 1;
        int base = 0;
        if (lane == leader) base = atomicAdd(outc, __popc(mask));
        base = __shfl_sync(mask, base, leader);
        outl[base + __popc(mask & ((1u << lane) - 1))] = p;
    }
}

// ---------------- fused persistent MIS (R10 verbatim) ----------------
__global__ void __launch_bounds__(512) k_mis_fused(const int* __restrict__ src,
                                                   const int* __restrict__ dst) {
    const int nb = gridDim.x;
    const int nt = nb * 512;
    const int gt = blockIdx.x * 512 + threadIdx.x;
    const int lane = threadIdx.x & 31;
    __shared__ int s_cnt, s_ep;
    if (threadIdx.x == 0) s_ep = atomicAdd(&g_barrel, 0);
    __syncthreads();
    int epoch = s_ep;

    for (int e = gt; e < EE; e += nt) {
        int s = src[e], d = dst[e];
        if (s == d) { g_block[s] = 1; continue; }
        atomicMax(&g_nmax[d], g_key[s]);
        atomicMax(&g_nmax[s], g_key[d]);
    }
    gbar(nb, epoch);
    for (int e = gt; e < EE; e += nt) {
        int s = src[e], d = dst[e];
        if (s == d) continue;
        if (!g_block[s] && g_akey[s] > g_nmax[s]) { g_mis[s] = 1; g_akey[d] = 0; }
        if (!g_block[d] && g_akey[d] > g_nmax[d]) { g_mis[d] = 1; g_akey[s] = 0; }
    }
    gbar(nb, epoch);

    int prev = EE + 1;
    unsigned long long* nmaxLast = g_nmax;
    for (int t = 1; t < MIS_ITERS; t++) {
        int ob = t & 1;
        unsigned long long* nmaxC = ob ? g_nmax2 : g_nmax;
        unsigned long long* nmaxN = ob ? g_nmax : g_nmax2;
        int2* outl = ob ? g_elB : g_elA;
        int* outc = &g_ecnt[ob];
        if (t == 1) {
            for (int e = gt; e - lane < EE; e += nt) {
                bool in = e < EE;
                int2 p = make_int2(0, 0);
                bool live = false;
                if (in) {
                    p.x = src[e]; p.y = dst[e];
                    if (p.x != p.y) {
                        unsigned long long ks = g_akey[p.x], kd = g_akey[p.y];
                        if (ks && kd && !g_mis[p.x] && !g_mis[p.y]) {
                            live = true;
                            atomicMax(&nmaxC[p.y], ks);
                            atomicMax(&nmaxC[p.x], kd);
                        }
                    }
                }
                wappend(live, p, outl, outc, lane);
            }
        } else {
            const int2* inl = ob ? g_elA : g_elB;
            int cin = g_ecnt[1 - ob];
            for (int e = gt; e - lane < cin; e += nt) {
                bool in = e < cin;
                int2 p = make_int2(0, 0);
                bool live = false;
                if (in) {
                    p = inl[e];
                    unsigned long long ks = g_akey[p.x], kd = g_akey[p.y];
                    if (ks && kd && !g_mis[p.x] && !g_mis[p.y]) {
                        live = true;
                        atomicMax(&nmaxC[p.y], ks);
                        atomicMax(&nmaxC[p.x], kd);
                    }
                }
                wappend(live, p, outl, outc, lane);
            }
        }
        gbar(nb, epoch);
        if (threadIdx.x == 0) s_cnt = g_ecnt[ob];
        __syncthreads();
        int cnt = s_cnt;
        nmaxLast = nmaxC;
        if (cnt == 0 || cnt == prev) break;
        prev = cnt;
        if (gt == 0) g_ecnt[1 - ob] = 0;
        for (int e = gt; e < cnt; e += nt) {
            int2 p = outl[e];
            if (!g_block[p.x] && g_akey[p.x] > nmaxC[p.x]) { g_mis[p.x] = 1; g_akey[p.y] = 0; }
            if (!g_block[p.y] && g_akey[p.y] > nmaxC[p.y]) { g_mis[p.y] = 1; g_akey[p.x] = 0; }
        }
        for (int i = gt; i < NN; i += nt) nmaxN[i] = 0ULL;
        gbar(nb, epoch);
    }

    for (int i = gt; i < NN; i += nt) {
        bool iso = g_akey[i] && !g_mis[i] && !g_block[i] && (nmaxLast[i] == 0ULL);
        if (iso) g_mis[i] = 1;
        g_nmax[i] = 0ULL;
    }
    gbar(nb, epoch);
    for (int e = gt; e < EE; e += nt) {
        int s = src[e], d = dst[e];
        if (g_mis[s]) atomicMax(&g_nmax[d], g_key[s]);
        if (g_mis[d]) atomicMax(&g_nmax[s], g_key[d]);
    }
}

// ---------------- zero x_pool region + cluster decode (post-MIS) ----------------
__global__ void k_zero_out(float* __restrict__ out, int out_size) {
    int t = blockIdx.x * blockDim.x + threadIdx.x;
    if (t < NN * CC / 4 && 4 * t + 3 < out_size)
        ((float4*)out)[t] = make_float4(0.f, 0.f, 0.f, 0.f);
    if (t < NN) {
        int cl;
        if (g_mis[t]) cl = t;
        else {
            unsigned long long b = g_nmax[t];
            cl = b ? (NN - 1 - (int)(unsigned)(b & 0xFFFFFFFFULL)) : t;
        }
        g_cluster[t] = cl;
    }
}

// ---------------- merged pool + tail: overlap L2-atomic pool with DRAM tail -------
__global__ void __launch_bounds__(256) k_pooltail(float* __restrict__ out,
                                                  const int* __restrict__ src,
                                                  const int* __restrict__ dst,
                                                  const float* __restrict__ ew,
                                                  const float* __restrict__ pos,
                                                  int out_size) {
    int gt = blockIdx.x * 256 + threadIdx.x;
    // pool section: warp per node (grid sized so grid*8 warps == NN exactly)
    {
        int node = gt >> 5, lane = gt & 31;
        if (node < NN) {
            int cl = g_cluster[node];
            if (g_mis[cl]) {
                float4 v = *(const float4*)(g_h1 + (size_t)node * CC + lane * 4);
                int* p = (int*)(out + (size_t)cl * CC + lane * 4);
                atomicMax(p + 0, __float_as_int(v.x));
                atomicMax(p + 1, __float_as_int(v.y));
                atomicMax(p + 2, __float_as_int(v.z));
                atomicMax(p + 3, __float_as_int(v.w));
            }
        }
    }
    // tail section: grid-stride over MIS-dependent + static output regions
    const int O1 = NN * CC;
    const int TAIL = 3 * EE + 5 * NN;
    int stride = gridDim.x * 256;
    for (int t = gt; t < TAIL; t += stride) {
        int o = O1 + t;
        if (o >= out_size) return;
        float val;
        if (t < EE) {
            val = (float)g_cluster[src[t]];
        } else if (t < 2 * EE) {
            val = (float)g_cluster[dst[t - EE]];
        } else if (t < 3 * EE) {
            val = ew[t - 2 * EE];
        } else if (t < 3 * EE + 3 * NN) {
            int j = t - 3 * EE;
            val = g_mis[j / 3] ? pos[j] : 0.f;
        } else if (t < 3 * EE + 4 * NN) {
            val = 0.f;  // batch
        } else {
            val = g_mis[t - (3 * EE + 4 * NN)] ? 1.f : 0.f;
        }
        out[o] = val;
    }
}

// ---------------- launch ----------------
extern "C" void kernel_launch(void* const* d_in, const int* in_sizes, int n_in,
                              void* d_out, int out_size) {
    const float* x   = (const float*)d_in[0];
    const int*   ei  = (const int*)d_in[1];
    const float* ew  = (const float*)d_in[2];
    const float* pos = (const float*)d_in[3];
    const float* Wr0 = (const float*)d_in[5];
    const float* Wm0 = (const float*)d_in[6];
    const float* Wp0 = (const float*)d_in[7];
    const float* b0  = (const float*)d_in[8];
    const float* g0  = (const float*)d_in[9];
    const float* be0 = (const float*)d_in[10];
    const float* Wr1 = (const float*)d_in[11];
    const float* Wm1 = (const float*)d_in[12];
    const float* Wp1 = (const float*)d_in[13];
    const float* b1  = (const float*)d_in[14];
    const float* g1  = (const float*)d_in[15];
    const float* be1 = (const float*)d_in[16];
    const float* wsc = (const float*)d_in[17];
    float* out = (float*)d_out;

    const int E = in_sizes[1] / 2;
    const int* src = ei;
    const int* dst = ei + E;
    (void)E;

    int sms = 148;
    cudaDeviceGetAttribute(&sms, cudaDevAttrMultiProcessorCount, 0);

    const int NB4   = (NN * CC / 4 + 255) / 256;
    const int EB    = (EE + 255) / 256;
    const int NWARP = (NN * 32 + 255) / 256;
    const int NBn   = (NN + 255) / 256;
    const int GGRID = (NN + 127) / 128;

    // ---- CSR build ----
    k_zero_deg<<<NBn, 256>>>();
    k_hist<<<EB, 256>>>(dst);
    k_scan<<<1, 1024>>>();
    k_scatter<<<EB, 256>>>(src, dst, ew);

    // ---- layer 0 ----
    k_spmm_pull<<<NWARP, 256>>>(x, pos, 0);
    k_gemm<<<GGRID, 256>>>(x, Wr0, Wm0, Wp0, b0, 0, 0);
    k_bnfin<<<1, 128>>>(g0, be0);

    // ---- layer 1 ----
    k_spmm_pull<<<NWARP, 256>>>(nullptr, nullptr, 1);
    k_gemm<<<GGRID, 256>>>(nullptr, Wr1, Wm1, Wp1, b1, 1, 1);
    k_bnfin<<<1, 128>>>(g1, be1);
    k_bnrelu_key<<<NWARP, 256>>>(wsc);

    // ---- fused persistent MIS + best-neighbor ----
    k_mis_fused<<<sms, 512>>>(src, dst);

    // ---- zero + cluster decode, then merged pool+tail ----
    k_zero_out<<<NB4, 256>>>(out, out_size);
    k_pooltail<<<NWARP, 256>>>(out, src, dst, ew, pos, out_size);
}